// round 2
// baseline (speedup 1.0000x reference)
#include <cuda_runtime.h>

#define B_DIM 4
#define L_DIM 512
#define D_DIM 768
#define KWIN  10
#define PDIM  50
#define RDIM  1586      // 2*768 + 50
#define NREL  21        // 2*K + 1
#define NPAIR 10642     // windowed pair count for L=512, K=10

// Scratch (static device globals -- runtime allocation is forbidden)
__device__ float g_A [B_DIM * L_DIM * RDIM];   // doc @ W1[0:768]
__device__ float g_C [B_DIM * L_DIM * RDIM];   // doc @ W1[768:1536]
__device__ float g_M [NREL * PDIM];            // collapsed kernel@emb table
__device__ float g_E2[NREL * RDIM];            // M @ W1[1536:1586] + b1

// -------------------------------------------------------------------------
// pairs are enumerated i-outer, j-inner over [max(0,i-K), min(L-1,i+K)]
__device__ __forceinline__ int pair_offset(int i) {
    if (i <= KWIN) return i * (KWIN + 1) + (i * (i - 1)) / 2;
    int off = 155 + (i - KWIN) * (2 * KWIN + 1);        // 155 = offset(K)
    if (i <= L_DIM - KWIN) return off;
    int d = i - (L_DIM - KWIN);
    return off - (d * (d + 1)) / 2;
}

// -------------------------------------------------------------------------
// M[u,p] = sum_v (L - |v-K|) * exp(-(u-v)^2) * pos_emb[v,p]
__global__ void k_relemb(const float* __restrict__ pos_emb) {
    int u = blockIdx.x, p = threadIdx.x;   // <<<21, 50>>>
    float acc = 0.f;
#pragma unroll
    for (int v = 0; v < NREL; ++v) {
        float w = (float)(L_DIM - abs(v - KWIN));
        float d = (float)(u - v);
        acc += w * expf(-d * d) * pos_emb[v * PDIM + p];
    }
    g_M[u * PDIM + p] = acc;
}

// E2[u,r] = b1[r] + sum_p M[u,p] * W1[(1536+p), r]
__global__ void k_e2(const float* __restrict__ W1, const float* __restrict__ b1) {
    __shared__ float sM[PDIM];
    int u = blockIdx.x;                    // <<<21, 256>>>
    if (threadIdx.x < PDIM) sM[threadIdx.x] = g_M[u * PDIM + threadIdx.x];
    __syncthreads();
    for (int r = threadIdx.x; r < RDIM; r += blockDim.x) {
        float acc = b1[r];
#pragma unroll
        for (int p = 0; p < PDIM; ++p)
            acc += sM[p] * W1[(2 * D_DIM + p) * RDIM + r];
        g_E2[u * RDIM + r] = acc;
    }
}

// -------------------------------------------------------------------------
// Out[m,n] = sum_k X[m,k] * W[k,n].  X: [2048,768] ld=768.  W: ld=RDIM.
// 128x128 block tile, BK=8, 256 threads, 8x8 per thread.
__global__ __launch_bounds__(256) void k_gemm(const float* __restrict__ X,
                                              const float* __restrict__ W,
                                              float* __restrict__ Out) {
    const int Kd = D_DIM, Nn = RDIM;
    __shared__ float As[8][128];
    __shared__ float Bs[8][128];
    int t = threadIdx.x;
    int m0 = blockIdx.y * 128;
    int n0 = blockIdx.x * 128;
    int arow = t >> 1, acol = (t & 1) * 4;
    int ty = t >> 4, tx = t & 15;
    float c[8][8] = {};

    for (int k0 = 0; k0 < Kd; k0 += 8) {
        float4 av = *reinterpret_cast<const float4*>(&X[(m0 + arow) * Kd + k0 + acol]);
        As[acol + 0][arow] = av.x; As[acol + 1][arow] = av.y;
        As[acol + 2][arow] = av.z; As[acol + 3][arow] = av.w;
#pragma unroll
        for (int it = 0; it < 2; ++it) {
            int idx = it * 256 + t;
            int kb = idx >> 6;
            int c2 = idx & 63;
            int gc = n0 + c2 * 2;
            float2 bv = make_float2(0.f, 0.f);
            if (gc + 1 < Nn)      // RDIM even, gc even -> pairwise guard suffices
                bv = *reinterpret_cast<const float2*>(&W[(k0 + kb) * Nn + gc]);
            Bs[kb][c2 * 2] = bv.x; Bs[kb][c2 * 2 + 1] = bv.y;
        }
        __syncthreads();
#pragma unroll
        for (int kk = 0; kk < 8; ++kk) {
            float a[8], b[8];
            *(float4*)&a[0] = *(const float4*)&As[kk][ty * 8];
            *(float4*)&a[4] = *(const float4*)&As[kk][ty * 8 + 4];
            *(float4*)&b[0] = *(const float4*)&Bs[kk][tx * 8];
            *(float4*)&b[4] = *(const float4*)&Bs[kk][tx * 8 + 4];
#pragma unroll
            for (int ii = 0; ii < 8; ++ii)
#pragma unroll
                for (int jj = 0; jj < 8; ++jj)
                    c[ii][jj] = fmaf(a[ii], b[jj], c[ii][jj]);
        }
        __syncthreads();
    }
#pragma unroll
    for (int ii = 0; ii < 8; ++ii) {
        int gm = m0 + ty * 8 + ii;
#pragma unroll
        for (int jj = 0; jj < 8; ++jj) {
            int gn = n0 + tx * 8 + jj;
            if (gn < Nn) Out[(long)gm * Nn + gn] = c[ii][jj];
        }
    }
}

// -------------------------------------------------------------------------
// Per (b,i): h[b,p,:] = relu(A[b,i,:] + C[b,j,:] + E2[rel,:]); pred = h.W2 + b2
__global__ __launch_bounds__(256) void k_pair(const float* __restrict__ W2,
                                              const float* __restrict__ b2p,
                                              float* __restrict__ pred,
                                              float* __restrict__ pos,
                                              float* __restrict__ h) {
    __shared__ float2 sA[RDIM / 2];
    __shared__ float2 sW[RDIM / 2];
    __shared__ float  sred[8];
    int b = blockIdx.x / L_DIM;
    int i = blockIdx.x % L_DIM;
    int t = threadIdx.x;

    const float2* Arow = (const float2*)&g_A[((long)b * L_DIM + i) * RDIM];
    const float2* W2v  = (const float2*)W2;
    for (int r = t; r < RDIM / 2; r += 256) { sA[r] = Arow[r]; sW[r] = W2v[r]; }
    __syncthreads();

    int jstart = max(0, i - KWIN);
    int jend   = min(L_DIM - 1, i + KWIN);
    int cnt    = jend - jstart + 1;
    int off    = pair_offset(i);
    float b2   = b2p[0];

    for (int jj = 0; jj < cnt; ++jj) {
        int j   = jstart + jj;
        int rel = j - i + KWIN;
        long p  = off + jj;
        const float2* Crow = (const float2*)&g_C[((long)b * L_DIM + j) * RDIM];
        const float2* Erow = (const float2*)&g_E2[(long)rel * RDIM];
        float2*       Hrow = (float2*)&h[((long)b * NPAIR + p) * RDIM];

        float acc = 0.f;
        for (int r = t; r < RDIM / 2; r += 256) {
            float2 a = sA[r], cc = Crow[r], e = Erow[r];
            float v0 = fmaxf(a.x + cc.x + e.x, 0.f);
            float v1 = fmaxf(a.y + cc.y + e.y, 0.f);
            Hrow[r] = make_float2(v0, v1);
            float2 w = sW[r];
            acc = fmaf(v0, w.x, acc);
            acc = fmaf(v1, w.y, acc);
        }
#pragma unroll
        for (int s = 16; s; s >>= 1) acc += __shfl_down_sync(0xffffffffu, acc, s);
        if ((t & 31) == 0) sred[t >> 5] = acc;
        __syncthreads();
        if (t < 8) {
            float v = sred[t];
#pragma unroll
            for (int s = 4; s; s >>= 1) v += __shfl_down_sync(0xffu, v, s);
            if (t == 0) pred[(long)b * NPAIR + p] = v + b2;
        }
        __syncthreads();
    }

    if (b == 0 && t < cnt) {
        int p = off + t;
        pos[2 * p]     = (float)(i + 1);
        pos[2 * p + 1] = (float)(jstart + t + 1);
    }
}

// -------------------------------------------------------------------------
extern "C" void kernel_launch(void* const* d_in, const int* in_sizes, int n_in,
                              void* d_out, int out_size) {
    const float* doc     = (const float*)d_in[0];  // [4,512,768]
    const float* pos_emb = (const float*)d_in[1];  // [21,50]
    const float* W1      = (const float*)d_in[2];  // [1586,1586]
    const float* b1      = (const float*)d_in[3];  // [1586]
    const float* W2      = (const float*)d_in[4];  // [1586]
    const float* b2      = (const float*)d_in[5];  // [1]

    float* out  = (float*)d_out;
    float* pred = out;                                   // [4, 10642]
    float* pos  = out + (long)B_DIM * NPAIR;             // [10642, 2]
    float* h    = pos + 2L * NPAIR;                      // [4, 10642, 1586]

    float *gA = nullptr, *gC = nullptr;
    cudaGetSymbolAddress((void**)&gA, g_A);
    cudaGetSymbolAddress((void**)&gC, g_C);

    k_relemb<<<NREL, PDIM>>>(pos_emb);
    k_e2<<<NREL, 256>>>(W1, b1);

    dim3 gg((RDIM + 127) / 128, (B_DIM * L_DIM) / 128);  // (13, 16)
    k_gemm<<<gg, 256>>>(doc, W1, gA);                       // A = doc @ W1[0:768]
    k_gemm<<<gg, 256>>>(doc, W1 + (long)D_DIM * RDIM, gC);  // C = doc @ W1[768:1536]

    k_pair<<<B_DIM * L_DIM, 256>>>(W2, b2, pred, pos, h);
}